// round 15
// baseline (speedup 1.0000x reference)
#include <cuda_runtime.h>
#include <cstdint>

#define BB 32
#define CC 384
#define TT 512
#define MF 6656   // MAX_FRAMES = 512*13
#define CPB 64    // channels per block

// ---------------------------------------------------------------------------
// Fused kernel: grid (13, CC/CPB=6, 32), block 128.
//   Phase 1: 128-thread warp+block scan over this batch's 512 repeat counts
//            -> inclusive cumsum in smem (bit-exact f32 front end).
//   Phase 2: tokens via one binary search + monotone refinement; warp token
//            bounds via mask-safe butterfly min/max; expand paths
//            (zero / shuffle-window / direct gather) over CPB channels,
//            streaming stores (__stcs).
// ---------------------------------------------------------------------------
__global__ void __launch_bounds__(128) fused_kernel(
        const float* __restrict__ x,
        const float* __restrict__ notepitch,
        const float* __restrict__ duration,
        float* __restrict__ out) {
    const int b    = blockIdx.z;
    const int c0   = blockIdx.y * CPB;
    const int tid  = threadIdx.x;        // 0..127
    const int lane = tid & 31;
    const int wid  = tid >> 5;           // 0..3
    const int p0   = blockIdx.x * 512 + tid * 4;

    __shared__ int   s[TT];      // inclusive cumsum of repeat counts
    __shared__ float sp[TT];     // pitch values (used only by y==0 blocks)
    __shared__ int   wsum[4];

    // ---- Phase 1: repeat counts + scan (each thread owns 4 tokens) ----
    const float4 d4 = *reinterpret_cast<const float4*>(duration + b * TT + 4 * tid);
    int r[4];
    {
        const float dv[4] = {d4.x, d4.y, d4.z, d4.w};
        #pragma unroll
        for (int j = 0; j < 4; ++j) {
            const float fr = 44100.0f * dv[j];
            float rf;
            if (fr - 1024.0f > 0.0f)
                rf = fmaxf((fr - 1024.0f) * (1.0f / 256.0f), 1.0f);  // /256 exact
            else
                rf = (dv[j] == 0.0f) ? 0.0f : 1.0f;
            r[j] = (int)rf;
        }
    }
    const int tsum = r[0] + r[1] + r[2] + r[3];
    int incl = tsum;
    #pragma unroll
    for (int o = 1; o < 32; o <<= 1) {
        const int v = __shfl_up_sync(0xffffffffu, incl, o);
        if (lane >= o) incl += v;
    }
    if (lane == 31) wsum[wid] = incl;

    if (blockIdx.y == 0) {
        const float4 np = *reinterpret_cast<const float4*>(notepitch + b * TT + 4 * tid);
        sp[4 * tid + 0] = (float)(int)np.x;
        sp[4 * tid + 1] = (float)(int)np.y;
        sp[4 * tid + 2] = (float)(int)np.z;
        sp[4 * tid + 3] = (float)(int)np.w;
    }
    __syncthreads();
    int woff = 0;
    #pragma unroll
    for (int i = 0; i < 4; ++i) woff += (i < wid) ? wsum[i] : 0;
    const int excl = woff + (incl - tsum);
    s[4 * tid + 0] = excl + r[0];
    s[4 * tid + 1] = excl + r[0] + r[1];
    s[4 * tid + 2] = excl + r[0] + r[1] + r[2];
    s[4 * tid + 3] = excl + tsum;
    __syncthreads();
    const int flen = s[TT - 1];

    // ---- Phase 2: tokens for this thread's 4 consecutive frames ----
    int tk[4];
    bool msk[4];
    {
        int idx = 0;
        if (p0 < flen) {
            #pragma unroll
            for (int step = 256; step > 0; step >>= 1) {
                const int cand = idx + step;
                if (cand <= TT && s[cand - 1] <= p0) idx = cand;
            }
        }
        #pragma unroll
        for (int j = 0; j < 4; ++j) {
            const int p = p0 + j;
            msk[j] = p < flen;
            if (msk[j]) {
                while (s[idx] <= p) ++idx;   // stays <= 511 while p < flen
            }
            tk[j] = idx;
        }
    }
    const bool m0 = msk[0], m1 = msk[1], m2 = msk[2], m3 = msk[3];
    const int  t0 = tk[0],  t1 = tk[1],  t2 = tk[2],  t3 = tk[3];

    // pitch + flen outputs (y==0 slice only)
    if (blockIdx.y == 0) {
        float* pitch_out = out + (size_t)BB * CC * MF + (size_t)b * MF;
        float4 pv;
        pv.x = m0 ? sp[t0] : 0.0f;
        pv.y = m1 ? sp[t1] : 0.0f;
        pv.z = m2 ? sp[t2] : 0.0f;
        pv.w = m3 ? sp[t3] : 0.0f;
        __stcs(reinterpret_cast<float4*>(pitch_out + p0), pv);
        if (blockIdx.x == 0 && tid == 0)
            out[(size_t)BB * CC * MF + (size_t)BB * MF + b] = (float)flen;
    }

    float* ob = out + ((size_t)b * CC + c0) * MF + p0;

    // warp min/max over VALID tokens only (mask-safe butterfly reduction)
    int mn = 0x7fffffff, mx = -1;
    if (m0) { mn = min(mn, t0); mx = max(mx, t0); }
    if (m1) { mn = min(mn, t1); mx = max(mx, t1); }
    if (m2) { mn = min(mn, t2); mx = max(mx, t2); }
    if (m3) { mn = min(mn, t3); mx = max(mx, t3); }
    #pragma unroll
    for (int o = 16; o > 0; o >>= 1) {
        mn = min(mn, __shfl_xor_sync(0xffffffffu, mn, o));
        mx = max(mx, __shfl_xor_sync(0xffffffffu, mx, o));
    }

    if (mx < 0) {
        // fully-masked warp: pure zero streaming stores
        const float4 z = make_float4(0.f, 0.f, 0.f, 0.f);
        #pragma unroll 8
        for (int c = 0; c < CPB; ++c)
            __stcs(reinterpret_cast<float4*>(ob + (size_t)c * MF), z);
        return;
    }

    const float* xb   = x + ((size_t)b * CC + c0) * TT;
    const int    span = mx - mn + 1;  // >= 1, warp-uniform

    if (span <= 32) {
        // shuffle gather: one coalesced 128B window load per channel.
        const int i0 = m0 ? (t0 - mn) : 0;
        const int i1 = m1 ? (t1 - mn) : 0;
        const int i2 = m2 ? (t2 - mn) : 0;
        const int i3 = m3 ? (t3 - mn) : 0;
        const bool inw = lane < span;

        #pragma unroll 4
        for (int c = 0; c < CPB; ++c) {
            const float* xr = xb + (size_t)c * TT;
            const float  w  = inw ? xr[mn + lane] : 0.0f;
            const float sh0 = __shfl_sync(0xffffffffu, w, i0);
            const float sh1 = __shfl_sync(0xffffffffu, w, i1);
            const float sh2 = __shfl_sync(0xffffffffu, w, i2);
            const float sh3 = __shfl_sync(0xffffffffu, w, i3);
            float4 v;
            v.x = m0 ? sh0 : 0.0f;
            v.y = m1 ? sh1 : 0.0f;
            v.z = m2 ? sh2 : 0.0f;
            v.w = m3 ? sh3 : 0.0f;
            __stcs(reinterpret_cast<float4*>(ob + (size_t)c * MF), v);
        }
    } else {
        // fallback: direct gmem gather (rare)
        const int a0 = m0 ? t0 : 0, a1 = m1 ? t1 : 0;
        const int a2 = m2 ? t2 : 0, a3 = m3 ? t3 : 0;
        #pragma unroll 4
        for (int c = 0; c < CPB; ++c) {
            const float* xr = xb + (size_t)c * TT;
            float4 v;
            v.x = m0 ? xr[a0] : 0.0f;
            v.y = m1 ? xr[a1] : 0.0f;
            v.z = m2 ? xr[a2] : 0.0f;
            v.w = m3 ? xr[a3] : 0.0f;
            __stcs(reinterpret_cast<float4*>(ob + (size_t)c * MF), v);
        }
    }
}

extern "C" void kernel_launch(void* const* d_in, const int* in_sizes, int n_in,
                              void* d_out, int out_size) {
    const float* x         = (const float*)d_in[0];
    const float* notepitch = (const float*)d_in[1];
    const float* duration  = (const float*)d_in[2];
    // d_in[3] = x_lengths: unused by the reference computation
    float* out = (float*)d_out;

    fused_kernel<<<dim3(MF / 512, CC / CPB, BB), 128>>>(x, notepitch, duration, out);
}

// round 16
// speedup vs baseline: 1.0597x; 1.0597x over previous
#include <cuda_runtime.h>
#include <cstdint>

#define BB 32
#define CC 384
#define TT 512
#define MF 6656  // MAX_FRAMES = 512*13

// ---------------------------------------------------------------------------
// Fused kernel: grid (13, 12, 32), block 128.  [R14 config = measured optimum]
//   Phase 1: 128-thread warp+block scan over this batch's 512 repeat counts
//            -> inclusive cumsum in smem (bit-exact f32 front end).
//   Phase 2: tokens via one binary search + monotone refinement; warp token
//            bounds via mask-safe butterfly min/max; expand paths
//            (zero / shuffle-window / direct gather), streaming stores.
// ---------------------------------------------------------------------------
__global__ void __launch_bounds__(128) fused_kernel(
        const float* __restrict__ x,
        const float* __restrict__ notepitch,
        const float* __restrict__ duration,
        float* __restrict__ out) {
    const int b    = blockIdx.z;
    const int c0   = blockIdx.y * 32;
    const int tid  = threadIdx.x;        // 0..127
    const int lane = tid & 31;
    const int wid  = tid >> 5;           // 0..3
    const int p0   = blockIdx.x * 512 + tid * 4;

    __shared__ int   s[TT];      // inclusive cumsum of repeat counts
    __shared__ float sp[TT];     // pitch values (used only by y==0 blocks)
    __shared__ int   wsum[4];

    // ---- Phase 1: repeat counts + scan (each thread owns 4 tokens) ----
    const float4 d4 = *reinterpret_cast<const float4*>(duration + b * TT + 4 * tid);
    int r[4];
    {
        const float dv[4] = {d4.x, d4.y, d4.z, d4.w};
        #pragma unroll
        for (int j = 0; j < 4; ++j) {
            const float fr = 44100.0f * dv[j];
            float rf;
            if (fr - 1024.0f > 0.0f)
                rf = fmaxf((fr - 1024.0f) * (1.0f / 256.0f), 1.0f);  // /256 exact
            else
                rf = (dv[j] == 0.0f) ? 0.0f : 1.0f;
            r[j] = (int)rf;
        }
    }
    const int tsum = r[0] + r[1] + r[2] + r[3];
    int incl = tsum;
    #pragma unroll
    for (int o = 1; o < 32; o <<= 1) {
        const int v = __shfl_up_sync(0xffffffffu, incl, o);
        if (lane >= o) incl += v;
    }
    if (lane == 31) wsum[wid] = incl;

    if (blockIdx.y == 0) {
        const float4 np = *reinterpret_cast<const float4*>(notepitch + b * TT + 4 * tid);
        sp[4 * tid + 0] = (float)(int)np.x;
        sp[4 * tid + 1] = (float)(int)np.y;
        sp[4 * tid + 2] = (float)(int)np.z;
        sp[4 * tid + 3] = (float)(int)np.w;
    }
    __syncthreads();
    int woff = 0;
    #pragma unroll
    for (int i = 0; i < 4; ++i) woff += (i < wid) ? wsum[i] : 0;
    const int excl = woff + (incl - tsum);
    s[4 * tid + 0] = excl + r[0];
    s[4 * tid + 1] = excl + r[0] + r[1];
    s[4 * tid + 2] = excl + r[0] + r[1] + r[2];
    s[4 * tid + 3] = excl + tsum;
    __syncthreads();
    const int flen = s[TT - 1];

    // ---- Phase 2: tokens for this thread's 4 consecutive frames ----
    int tk[4];
    bool msk[4];
    {
        int idx = 0;
        if (p0 < flen) {
            #pragma unroll
            for (int step = 256; step > 0; step >>= 1) {
                const int cand = idx + step;
                if (cand <= TT && s[cand - 1] <= p0) idx = cand;
            }
        }
        #pragma unroll
        for (int j = 0; j < 4; ++j) {
            const int p = p0 + j;
            msk[j] = p < flen;
            if (msk[j]) {
                while (s[idx] <= p) ++idx;   // stays <= 511 while p < flen
            }
            tk[j] = idx;
        }
    }
    const bool m0 = msk[0], m1 = msk[1], m2 = msk[2], m3 = msk[3];
    const int  t0 = tk[0],  t1 = tk[1],  t2 = tk[2],  t3 = tk[3];

    // pitch + flen outputs (y==0 slice only)
    if (blockIdx.y == 0) {
        float* pitch_out = out + (size_t)BB * CC * MF + (size_t)b * MF;
        float4 pv;
        pv.x = m0 ? sp[t0] : 0.0f;
        pv.y = m1 ? sp[t1] : 0.0f;
        pv.z = m2 ? sp[t2] : 0.0f;
        pv.w = m3 ? sp[t3] : 0.0f;
        __stcs(reinterpret_cast<float4*>(pitch_out + p0), pv);
        if (blockIdx.x == 0 && tid == 0)
            out[(size_t)BB * CC * MF + (size_t)BB * MF + b] = (float)flen;
    }

    float* ob = out + ((size_t)b * CC + c0) * MF + p0;

    // warp min/max over VALID tokens only (mask-safe butterfly reduction)
    int mn = 0x7fffffff, mx = -1;
    if (m0) { mn = min(mn, t0); mx = max(mx, t0); }
    if (m1) { mn = min(mn, t1); mx = max(mx, t1); }
    if (m2) { mn = min(mn, t2); mx = max(mx, t2); }
    if (m3) { mn = min(mn, t3); mx = max(mx, t3); }
    #pragma unroll
    for (int o = 16; o > 0; o >>= 1) {
        mn = min(mn, __shfl_xor_sync(0xffffffffu, mn, o));
        mx = max(mx, __shfl_xor_sync(0xffffffffu, mx, o));
    }

    if (mx < 0) {
        // fully-masked warp: pure zero streaming stores
        const float4 z = make_float4(0.f, 0.f, 0.f, 0.f);
        #pragma unroll
        for (int c = 0; c < 32; ++c)
            __stcs(reinterpret_cast<float4*>(ob + (size_t)c * MF), z);
        return;
    }

    const float* xb   = x + ((size_t)b * CC + c0) * TT;
    const int    span = mx - mn + 1;  // >= 1, warp-uniform

    if (span <= 32) {
        // shuffle gather: one coalesced 128B window load per channel.
        // Window load unpredicated (clamped index); shuffles convergent.
        const int wi = min(mn + lane, TT - 1);
        const int i0 = m0 ? (t0 - mn) : 0;
        const int i1 = m1 ? (t1 - mn) : 0;
        const int i2 = m2 ? (t2 - mn) : 0;
        const int i3 = m3 ? (t3 - mn) : 0;

        #pragma unroll 4
        for (int c = 0; c < 32; ++c) {
            const float* xr = xb + (size_t)c * TT;
            const float  w  = xr[wi];
            const float sh0 = __shfl_sync(0xffffffffu, w, i0);
            const float sh1 = __shfl_sync(0xffffffffu, w, i1);
            const float sh2 = __shfl_sync(0xffffffffu, w, i2);
            const float sh3 = __shfl_sync(0xffffffffu, w, i3);
            float4 v;
            v.x = m0 ? sh0 : 0.0f;
            v.y = m1 ? sh1 : 0.0f;
            v.z = m2 ? sh2 : 0.0f;
            v.w = m3 ? sh3 : 0.0f;
            __stcs(reinterpret_cast<float4*>(ob + (size_t)c * MF), v);
        }
    } else {
        // fallback: direct gmem gather (rare)
        const int a0 = m0 ? t0 : 0, a1 = m1 ? t1 : 0;
        const int a2 = m2 ? t2 : 0, a3 = m3 ? t3 : 0;
        #pragma unroll 4
        for (int c = 0; c < 32; ++c) {
            const float* xr = xb + (size_t)c * TT;
            float4 v;
            v.x = m0 ? xr[a0] : 0.0f;
            v.y = m1 ? xr[a1] : 0.0f;
            v.z = m2 ? xr[a2] : 0.0f;
            v.w = m3 ? xr[a3] : 0.0f;
            __stcs(reinterpret_cast<float4*>(ob + (size_t)c * MF), v);
        }
    }
}

extern "C" void kernel_launch(void* const* d_in, const int* in_sizes, int n_in,
                              void* d_out, int out_size) {
    const float* x         = (const float*)d_in[0];
    const float* notepitch = (const float*)d_in[1];
    const float* duration  = (const float*)d_in[2];
    // d_in[3] = x_lengths: unused by the reference computation
    float* out = (float*)d_out;

    fused_kernel<<<dim3(MF / 512, CC / 32, BB), 128>>>(x, notepitch, duration, out);
}